// round 14
// baseline (speedup 1.0000x reference)
#include <cuda_runtime.h>
#include <cuda_fp16.h>
#include <cstdint>

#define NC   4096
#define ND   2048
#define NTOT 6144
#define HIDDEN 512
#define NHEAD 8
#define HD   64
#define PADH 72   // half-element row stride for smem tiles

__device__ __half g_xhi[NTOT*HIDDEN], g_xlo[NTOT*HIDDEN];   // features, pre-split
__device__ float g_q  [NTOT*HIDDEN];
__device__ __half g_khi[NTOT*HIDDEN], g_klo[NTOT*HIDDEN];   // K, pre-split at GEMM epilogue
__device__ float g_v  [NTOT*HIDDEN];
__device__ __half g_vTh[HIDDEN*NTOT];    // [hid][row], f16
__device__ float g_att[NTOT*HIDDEN];
__device__ float g_h  [NTOT*HIDDEN];
__device__ __half g_WtQh[HIDDEN*HIDDEN], g_WtQl[HIDDEN*HIDDEN];   // Wt[j][k] hi/lo
__device__ __half g_WtKh[HIDDEN*HIDDEN], g_WtKl[HIDDEN*HIDDEN];
__device__ __half g_WtVh[HIDDEN*HIDDEN], g_WtVl[HIDDEN*HIDDEN];
__device__ __half g_WtUh[HIDDEN*2*HIDDEN], g_WtUl[HIDDEN*2*HIDDEN];
__device__ unsigned g_adj [NC*(ND/32)];
__device__ unsigned g_adjT[ND*(NC/32)];
__device__ float g_qn  [NTOT*NHEAD];
__device__ float g_kmax[2*NHEAD];
__device__ float g_ps[48*HIDDEN];
__device__ float g_pq[48*HIDDEN];
__device__ float g_scale[HIDDEN];
__device__ float g_shift[HIDDEN];

// ---------------- mma helpers -------------------------------------------------
__device__ __forceinline__ uint32_t s2u(const void* p) {
    uint32_t a;
    asm("{ .reg .u64 t; cvta.to.shared.u64 t, %1; cvt.u32.u64 %0, t; }" : "=r"(a) : "l"(p));
    return a;
}
__device__ __forceinline__ void mma_f16(float* d, const unsigned* a, const unsigned* b) {
    asm volatile("mma.sync.aligned.m16n8k16.row.col.f32.f16.f16.f32 "
        "{%0,%1,%2,%3}, {%4,%5,%6,%7}, {%8,%9}, {%0,%1,%2,%3};"
        : "+f"(d[0]), "+f"(d[1]), "+f"(d[2]), "+f"(d[3])
        : "r"(a[0]), "r"(a[1]), "r"(a[2]), "r"(a[3]), "r"(b[0]), "r"(b[1]));
}
__device__ __forceinline__ void ldmA(unsigned* a, uint32_t addr) {
    asm volatile("ldmatrix.sync.aligned.m8n8.x4.shared.b16 {%0,%1,%2,%3}, [%4];"
        : "=r"(a[0]), "=r"(a[1]), "=r"(a[2]), "=r"(a[3]) : "r"(addr));
}
__device__ __forceinline__ void h_split(float x, __half& hi, __half& lo) {
    hi = __float2half_rn(x);
    lo = __float2half_rn(x - __half2float(hi));
}

// ---------------- feature pre-split: x -> xhi/xlo -----------------------------
__global__ void split_x_kernel(const float* __restrict__ cf, const float* __restrict__ df) {
    int f = blockIdx.x * blockDim.x + threadIdx.x;     // over NTOT*HIDDEN/8
    if (f >= NTOT * HIDDEN / 8) return;
    size_t ofs = (size_t)f * 8;
    const size_t nce = (size_t)NC * HIDDEN;
    const float* src = (ofs < nce) ? cf + ofs : df + (ofs - nce);
    __half hbuf[8], lbuf[8];
    #pragma unroll
    for (int i = 0; i < 8; i += 4) {
        float4 v = *(const float4*)(src + i);
        h_split(v.x, hbuf[i],   lbuf[i]);
        h_split(v.y, hbuf[i+1], lbuf[i+1]);
        h_split(v.z, hbuf[i+2], lbuf[i+2]);
        h_split(v.w, hbuf[i+3], lbuf[i+3]);
    }
    *(uint4*)(g_xhi + ofs) = *(const uint4*)hbuf;
    *(uint4*)(g_xlo + ofs) = *(const uint4*)lbuf;
}

// ---------------- single-pass adjacency pack (both orientations) -------------
__global__ void pack_both_kernel(const int* __restrict__ cd) {
    int gw = (blockIdx.x * blockDim.x + threadIdx.x) >> 5;
    int lane = threadIdx.x & 31;
    if (gw >= (NC/32) * (ND/32)) return;
    int tr = gw / (ND/32), tc = gw % (ND/32);
    unsigned colbits = 0;
    #pragma unroll 4
    for (int r = 0; r < 32; r++) {
        int row = tr * 32 + r;
        int v = cd[(size_t)row * ND + tc * 32 + lane];
        unsigned word = __ballot_sync(0xFFFFFFFFu, v != 0);
        if (lane == r) g_adj[(size_t)row * (ND/32) + tc] = word;
        colbits |= (v != 0 ? 1u : 0u) << r;
    }
    g_adjT[(size_t)(tc * 32 + lane) * (NC/32) + tr] = colbits;
}

// ---------------- weight transpose + f16 hi/lo split --------------------------
__global__ void transpose_split_kernel(const float* __restrict__ in, int outSel, int R, int C) {
    __shared__ float t[32][33];
    __half* outh = (outSel == 0) ? g_WtQh : (outSel == 1) ? g_WtKh : (outSel == 2) ? g_WtVh : g_WtUh;
    __half* outl = (outSel == 0) ? g_WtQl : (outSel == 1) ? g_WtKl : (outSel == 2) ? g_WtVl : g_WtUl;
    int bx = blockIdx.x * 32, by = blockIdx.y * 32;
    int x = bx + threadIdx.x, y = by + threadIdx.y;
    #pragma unroll
    for (int i = 0; i < 32; i += 8) t[threadIdx.y + i][threadIdx.x] = in[(size_t)(y + i) * C + x];
    __syncthreads();
    x = by + threadIdx.x; y = bx + threadIdx.y;
    #pragma unroll
    for (int i = 0; i < 32; i += 8) {
        float v = t[threadIdx.x][threadIdx.y + i];
        __half hi, lo; h_split(v, hi, lo);
        outh[(size_t)(y + i) * R + x] = hi;
        outl[(size_t)(y + i) * R + x] = lo;
    }
}

// ---------------- V transpose fp32 -> f16: g_vTh[hid][row] --------------------
__global__ void transpose_v_kernel() {
    __shared__ float t[32][33];
    int bx = blockIdx.x * 32, by = blockIdx.y * 32;  // bx: hid, by: token
    int x = bx + threadIdx.x, y = by + threadIdx.y;
    #pragma unroll
    for (int i = 0; i < 32; i += 8) t[threadIdx.y + i][threadIdx.x] = g_v[(size_t)(y + i) * HIDDEN + x];
    __syncthreads();
    x = by + threadIdx.x; y = bx + threadIdx.y;
    #pragma unroll
    for (int i = 0; i < 32; i += 8)
        g_vTh[(size_t)(y + i) * NTOT + x] = __float2half_rn(t[threadIdx.x][threadIdx.y + i]);
}

// ---------------- norms / bounds ----------------------------------------------
__global__ void qn_kernel() {
    int idx = blockIdx.x * blockDim.x + threadIdx.x;
    if (idx >= NTOT * NHEAD) return;
    int row = idx >> 3, h = idx & 7;
    const float4* p = (const float4*)(g_q + (size_t)row * HIDDEN + h * HD);
    float s = 0.f;
    #pragma unroll
    for (int i = 0; i < 16; i++) { float4 v = p[i]; s += v.x*v.x + v.y*v.y + v.z*v.z + v.w*v.w; }
    g_qn[idx] = sqrtf(s);
}
__global__ void kmax_kernel() {
    int head = blockIdx.x, side = blockIdx.y;
    int r0 = side ? NC : 0, nr = side ? ND : NC;
    int tid = threadIdx.x;
    float mx = 0.f;
    for (int r = tid; r < nr; r += 256) {
        const __half2* ph = (const __half2*)(g_khi + (size_t)(r0 + r) * HIDDEN + head * HD);
        const __half2* pl = (const __half2*)(g_klo + (size_t)(r0 + r) * HIDDEN + head * HD);
        float s = 0.f;
        #pragma unroll
        for (int i = 0; i < 32; i++) {
            float2 a = __half22float2(ph[i]);
            float2 b = __half22float2(pl[i]);
            float x = a.x + b.x, y = a.y + b.y;
            s += x * x + y * y;
        }
        mx = fmaxf(mx, s);
    }
    __shared__ float red[256];
    red[tid] = mx; __syncthreads();
    for (int o = 128; o; o >>= 1) { if (tid < o) red[tid] = fmaxf(red[tid], red[tid + o]); __syncthreads(); }
    if (tid == 0) g_kmax[side * 8 + head] = sqrtf(red[0]);
}

// ---------------- f16x3 mma GEMM ----------------------------------------------
// C = A @ W + bias. A cols<512: pre-split features (uint4 copies); cols>=512: g_att fp32.
// outSel: 0 q(fp32), 1 k(pre-split hi/lo), 2 v(fp32), 3 h(fp32).
__global__ void __launch_bounds__(256, 2)
gemm_f16(const float* __restrict__ bias, int wSel, int outSel, int Ktot)
{
    extern __shared__ __half sh[];
    __half* Ahi = sh;                    // [128][PADH]
    __half* Alo = Ahi + 128*PADH;
    __half* Bhi = Alo + 128*PADH;        // [128 n][PADH]
    __half* Blo = Bhi + 128*PADH;
    const __half* Wth = (wSel == 0) ? g_WtQh : (wSel == 1) ? g_WtKh : (wSel == 2) ? g_WtVh : g_WtUh;
    const __half* Wtl = (wSel == 0) ? g_WtQl : (wSel == 1) ? g_WtKl : (wSel == 2) ? g_WtVl : g_WtUl;

    const int tid = threadIdx.x, lane = tid & 31, w = tid >> 5;
    const int wm = w & 3, wn = w >> 2;
    const int rowBase = blockIdx.y * 128, colBase = blockIdx.x * 128;

    float acc[2][8][4];
    #pragma unroll
    for (int mi = 0; mi < 2; mi++)
        #pragma unroll
        for (int nt = 0; nt < 8; nt++)
            #pragma unroll
            for (int j = 0; j < 4; j++) acc[mi][nt][j] = 0.f;

    uint32_t addrA[2];
    #pragma unroll
    for (int mi = 0; mi < 2; mi++)
        addrA[mi] = s2u(Ahi) + (uint32_t)(((wm*32 + mi*16 + (lane & 15)) * PADH + (lane >> 4) * 8) * 2);
    const uint32_t dAlo = (uint32_t)(128 * PADH * 2);

    for (int kc = 0; kc < Ktot / 64; kc++) {
        if (kc < 8) {
            // A tile from pre-split features: pure uint4 copies
            #pragma unroll
            for (int i = 0; i < 4; i++) {
                int f = tid + i * 256;
                int r = f >> 3, c = (f & 7) * 8;
                size_t gofs = (size_t)(rowBase + r) * HIDDEN + kc * 64 + c;
                *(uint4*)(Ahi + r * PADH + c) = *(const uint4*)(g_xhi + gofs);
                *(uint4*)(Alo + r * PADH + c) = *(const uint4*)(g_xlo + gofs);
            }
        } else {
            // A tile from g_att (fp32) with split
            #pragma unroll
            for (int i = 0; i < 8; i++) {
                int f = tid + i * 256;
                int r = f >> 4, c = (f & 15) * 4;
                float4 v = *(const float4*)(g_att + (size_t)(rowBase + r) * HIDDEN + (kc - 8) * 64 + c);
                __half h0,h1,h2,h3,l0,l1,l2,l3;
                h_split(v.x,h0,l0); h_split(v.y,h1,l1); h_split(v.z,h2,l2); h_split(v.w,h3,l3);
                __half* ah = Ahi + r * PADH + c;
                __half* al = Alo + r * PADH + c;
                ah[0]=h0; ah[1]=h1; ah[2]=h2; ah[3]=h3;
                al[0]=l0; al[1]=l1; al[2]=l2; al[3]=l3;
            }
        }
        // B tile 128(n)x64(k): pre-split, pure uint4 copies
        #pragma unroll
        for (int i = 0; i < 4; i++) {
            int f = tid + i * 256;
            int r = f >> 3, c = (f & 7) * 8;
            size_t gofs = (size_t)(colBase + r) * Ktot + kc * 64 + c;
            *(uint4*)(Bhi + r * PADH + c) = *(const uint4*)(Wth + gofs);
            *(uint4*)(Blo + r * PADH + c) = *(const uint4*)(Wtl + gofs);
        }
        __syncthreads();

        #pragma unroll
        for (int ks = 0; ks < 4; ks++) {
            unsigned ahi[2][4], alo[2][4];
            #pragma unroll
            for (int mi = 0; mi < 2; mi++) {
                ldmA(ahi[mi], addrA[mi] + ks * 32);
                ldmA(alo[mi], addrA[mi] + dAlo + ks * 32);
            }
            #pragma unroll
            for (int nt = 0; nt < 8; nt++) {
                const __half* bp = Bhi + (wn*64 + nt*8 + (lane >> 2)) * PADH + ks*16 + (lane & 3)*2;
                const __half* bq = Blo + (wn*64 + nt*8 + (lane >> 2)) * PADH + ks*16 + (lane & 3)*2;
                unsigned bh[2] = { *(const unsigned*)bp, *(const unsigned*)(bp + 8) };
                unsigned bl[2] = { *(const unsigned*)bq, *(const unsigned*)(bq + 8) };
                #pragma unroll
                for (int mi = 0; mi < 2; mi++) {
                    mma_f16(acc[mi][nt], ahi[mi], bh);
                    mma_f16(acc[mi][nt], ahi[mi], bl);
                    mma_f16(acc[mi][nt], alo[mi], bh);
                }
            }
        }
        __syncthreads();
    }
    #pragma unroll
    for (int mi = 0; mi < 2; mi++) {
        int row = rowBase + wm*32 + mi*16 + (lane >> 2);
        #pragma unroll
        for (int nt = 0; nt < 8; nt++) {
            int col = colBase + wn*64 + nt*8 + (lane & 3)*2;
            float b0 = bias[col], b1 = bias[col + 1];
            float v00 = acc[mi][nt][0] + b0, v01 = acc[mi][nt][1] + b1;
            float v10 = acc[mi][nt][2] + b0, v11 = acc[mi][nt][3] + b1;
            if (outSel == 1) {
                __half h00,h01,h10,h11,l00,l01,l10,l11;
                h_split(v00,h00,l00); h_split(v01,h01,l01);
                h_split(v10,h10,l10); h_split(v11,h11,l11);
                *(__half2*)(g_khi + (size_t)row * HIDDEN + col)       = __halves2half2(h00, h01);
                *(__half2*)(g_klo + (size_t)row * HIDDEN + col)       = __halves2half2(l00, l01);
                *(__half2*)(g_khi + (size_t)(row + 8) * HIDDEN + col) = __halves2half2(h10, h11);
                *(__half2*)(g_klo + (size_t)(row + 8) * HIDDEN + col) = __halves2half2(l10, l11);
            } else {
                float* C = (outSel == 0) ? g_q : (outSel == 2) ? g_v : g_h;
                *(float2*)(C + (size_t)row * HIDDEN + col) = make_float2(v00, v01);
                *(float2*)(C + (size_t)(row + 8) * HIDDEN + col) = make_float2(v10, v11);
            }
        }
    }
}

// ---------------- f16 mma flash attention (R8 shape, occupancy 2) -------------
// flat grid 384: bid<128 d-side (head=bid>>4, qt=bid&15), else c-side
// (r=bid-128, head=r>>5, qt=r&31). 256 thr, warp w: 16 q rows.
__global__ void __launch_bounds__(256, 2)
attn_mma()
{
    extern __shared__ __half smh[];
    __half* Qhi = smh;                   // [128][PADH]
    __half* Qlo = Qhi + 128*PADH;
    __half* Khi = Qlo + 128*PADH;        // [64 key][PADH d]
    __half* Klo = Khi + 64*PADH;
    __half* Vt  = Klo + 64*PADH;         // [64 d][PADH key]
    __half* Pm  = Vt  + 64*PADH;         // [128][PADH]
    unsigned* Mw = (unsigned*)(Pm + 128*PADH);   // [128][2]

    const int tid = threadIdx.x, lane = tid & 31, w = tid >> 5;
    const int bid = blockIdx.x;
    const bool dside = (bid < 128);
    int head, qt;
    if (dside) { head = bid >> 4; qt = bid & 15; }
    else { int r = bid - 128; head = r >> 5; qt = r & 31; }
    const int qbase = dside ? NC + qt * 128 : qt * 128;
    const int kbase = dside ? 0 : NC;
    const int nkeys = dside ? NC : ND;
    const int qr0 = w * 16;

    // load Q tile, split hi/lo (once per CTA)
    #pragma unroll
    for (int i = 0; i < 8; i++) {
        int f = tid + i * 256;
        int r = f >> 4, c = (f & 15) * 4;
        float4 v = *(const float4*)(g_q + (size_t)(qbase + r) * HIDDEN + head * HD + c);
        __half h0,h1,h2,h3,l0,l1,l2,l3;
        h_split(v.x,h0,l0); h_split(v.y,h1,l1); h_split(v.z,h2,l2); h_split(v.w,h3,l3);
        __half* qh = Qhi + r * PADH + c;
        __half* ql = Qlo + r * PADH + c;
        qh[0]=h0; qh[1]=h1; qh[2]=h2; qh[3]=h3;
        ql[0]=l0; ql[1]=l1; ql[2]=l2; ql[3]=l3;
    }
    __syncthreads();

    const int rA = qr0 + (lane >> 2), rB = rA + 8;
    const float kmx = g_kmax[(dside ? 0 : 8) + head];
    const float MqA = g_qn[(qbase + rA) * NHEAD + head] * kmx * 0.125f;
    const float MqB = g_qn[(qbase + rB) * NHEAD + head] * kmx * 0.125f;
    const unsigned* mb = dside ? g_adjT + (size_t)(qbase - NC + tid) * (NC/32)
                               : g_adj  + (size_t)(qbase + tid) * (ND/32);

    const uint32_t aoff = (uint32_t)(((qr0 + (lane & 15)) * PADH + (lane >> 4) * 8) * 2);
    const uint32_t addrQhi = s2u(Qhi) + aoff;
    const uint32_t addrQlo = s2u(Qlo) + aoff;
    const uint32_t addrP   = s2u(Pm)  + aoff;

    float oacc[8][4];
    #pragma unroll
    for (int n = 0; n < 8; n++)
        #pragma unroll
        for (int j = 0; j < 4; j++) oacc[n][j] = 0.f;
    float lA = 0.f, lB = 0.f;

    #pragma unroll 1
    for (int kb = 0; kb < nkeys; kb += 64) {
        // K hi/lo + V^T tiles: all pure uint4 copies
        #pragma unroll
        for (int i = 0; i < 2; i++) {
            int f = tid + i * 256;
            int r = f >> 3, c = (f & 7) * 8;
            size_t kofs = (size_t)(kbase + kb + r) * HIDDEN + head * HD + c;
            *(uint4*)(Khi + r * PADH + c) = *(const uint4*)(g_khi + kofs);
            *(uint4*)(Klo + r * PADH + c) = *(const uint4*)(g_klo + kofs);
            *(uint4*)(Vt + r * PADH + c) =
                *(const uint4*)(g_vTh + (size_t)(head * HD + r) * NTOT + kbase + kb + c);
        }
        if (tid < 128) {
            Mw[tid * 2]     = mb[(kb >> 5)];
            Mw[tid * 2 + 1] = mb[(kb >> 5) + 1];
        }
        __syncthreads();

        // ---- S = Q K^T (f16 x3) ----
        float sacc[8][4];
        #pragma unroll
        for (int n = 0; n < 8; n++)
            #pragma unroll
            for (int j = 0; j < 4; j++) sacc[n][j] = 0.f;
        #pragma unroll
        for (int ks = 0; ks < 4; ks++) {
            unsigned ahi[4], alo[4];
            ldmA(ahi, addrQhi + ks * 32);
            ldmA(alo, addrQlo + ks * 32);
            #pragma unroll
            for (int nt = 0; nt < 8; nt++) {
                const __half* bp = Khi + (nt*8 + (lane >> 2)) * PADH + ks*16 + (lane & 3)*2;
                const __half* bq = Klo + (nt*8 + (lane >> 2)) * PADH + ks*16 + (lane & 3)*2;
                unsigned bh[2] = { *(const unsigned*)bp, *(const unsigned*)(bp + 8) };
                unsigned bl[2] = { *(const unsigned*)bq, *(const unsigned*)(bq + 8) };
                mma_f16(sacc[nt], ahi, bh);
                mma_f16(sacc[nt], ahi, bl);
                mma_f16(sacc[nt], alo, bh);
            }
        }
        // ---- softmax epilogue (single pass, bound-shifted) ----
        #pragma unroll
        for (int n = 0; n < 8; n++) {
            int colb = n * 8 + 2 * (lane & 3);
            unsigned mwA = Mw[rA * 2 + (colb >> 5)];
            unsigned mwB = Mw[rB * 2 + (colb >> 5)];
            int bit = colb & 31;
            float p0 = ((mwA >> bit) & 1u)       ? __expf(sacc[n][0] * 0.125f - MqA) : 0.f;
            float p1 = ((mwA >> (bit + 1)) & 1u) ? __expf(sacc[n][1] * 0.125f - MqA) : 0.f;
            float p2 = ((mwB >> bit) & 1u)       ? __expf(sacc[n][2] * 0.125f - MqB) : 0.f;
            float p3 = ((mwB >> (bit + 1)) & 1u) ? __expf(sacc[n][3] * 0.125f - MqB) : 0.f;
            lA += p0 + p1; lB += p2 + p3;
            *(__half2*)(Pm + rA * PADH + colb) = __floats2half2_rn(p0, p1);
            *(__half2*)(Pm + rB * PADH + colb) = __floats2half2_rn(p2, p3);
        }
        __syncwarp();
        // ---- O += P V (single f16) ----
        #pragma unroll
        for (int ks = 0; ks < 4; ks++) {
            unsigned ap[4];
            ldmA(ap, addrP + ks * 32);
            #pragma unroll
            for (int nt = 0; nt < 8; nt++) {
                const __half* vp = Vt + (nt*8 + (lane >> 2)) * PADH + ks*16 + (lane & 3)*2;
                unsigned bv[2] = { *(const unsigned*)vp, *(const unsigned*)(vp + 8) };
                mma_f16(oacc[nt], ap, bv);
            }
        }
        __syncthreads();
    }

    lA += __shfl_xor_sync(0xFFFFFFFFu, lA, 1);
    lA += __shfl_xor_sync(0xFFFFFFFFu, lA, 2);
    lB += __shfl_xor_sync(0xFFFFFFFFu, lB, 1);
    lB += __shfl_xor_sync(0xFFFFFFFFu, lB, 2);
    float invA = (lA > 0.f) ? 1.f / lA : 0.f;
    float invB = (lB > 0.f) ? 1.f / lB : 0.f;

    #pragma unroll
    for (int n = 0; n < 8; n++) {
        int colb = head * HD + n * 8 + 2 * (lane & 3);
        *(float2*)(g_att + (size_t)(qbase + rA) * HIDDEN + colb) =
            make_float2(oacc[n][0] * invA, oacc[n][1] * invA);
        *(float2*)(g_att + (size_t)(qbase + rB) * HIDDEN + colb) =
            make_float2(oacc[n][2] * invB, oacc[n][3] * invB);
    }
}

// ---------------- BatchNorm + ReLU -------------------------------------------
__global__ void bn_partial_kernel() {
    int c = threadIdx.x, g = blockIdx.x;
    float s = 0.f, q = 0.f;
    const float* p = g_h + (size_t)g * 128 * HIDDEN + c;
    #pragma unroll 4
    for (int r = 0; r < 128; r++) { float x = p[(size_t)r * HIDDEN]; s += x; q += x * x; }
    g_ps[g * HIDDEN + c] = s;
    g_pq[g * HIDDEN + c] = q;
}
__global__ void bn_final_kernel(const float* __restrict__ gamma, const float* __restrict__ beta) {
    int c = threadIdx.x;
    float s = 0.f, q = 0.f;
    #pragma unroll
    for (int g = 0; g < 48; g++) { s += g_ps[g * HIDDEN + c]; q += g_pq[g * HIDDEN + c]; }
    const float invN = 1.f / (float)NTOT;
    float mu = s * invN, var = q * invN - mu * mu;
    float sc = gamma[c] * rsqrtf(var + 1e-5f);
    g_scale[c] = sc; g_shift[c] = beta[c] - mu * sc;
}
__global__ void bn_apply_kernel(float4* __restrict__ out) {
    int i = blockIdx.x * blockDim.x + threadIdx.x;
    float4 hv = ((const float4*)g_h)[i];
    int c = (i * 4) & (HIDDEN - 1);
    out[i] = make_float4(fmaxf(0.f, hv.x * g_scale[c]   + g_shift[c]),
                         fmaxf(0.f, hv.y * g_scale[c+1] + g_shift[c+1]),
                         fmaxf(0.f, hv.z * g_scale[c+2] + g_shift[c+2]),
                         fmaxf(0.f, hv.w * g_scale[c+3] + g_shift[c+3]));
}

// ---------------- launch ------------------------------------------------------
extern "C" void kernel_launch(void* const* d_in, const int* in_sizes, int n_in,
                              void* d_out, int out_size)
{
    const float* c_feat = (const float*)d_in[0];
    const float* d_feat = (const float*)d_in[1];
    const int*   cd     = (const int*)  d_in[2];
    const float* Wq = (const float*)d_in[3];  const float* bq = (const float*)d_in[4];
    const float* Wk = (const float*)d_in[5];  const float* bk = (const float*)d_in[6];
    const float* Wv = (const float*)d_in[7];  const float* bv = (const float*)d_in[8];
    const float* Wu = (const float*)d_in[9];  const float* bu = (const float*)d_in[10];
    const float* gamma = (const float*)d_in[11];
    const float* beta  = (const float*)d_in[12];
    float* out = (float*)d_out;

    const int GSM = 4 * 128 * PADH * 2;                          // 73728 B
    const int ASM = (128*2 + 64*3 + 128) * PADH * 2 + 128*2*4;   // 83968 B
    static int configured = -1;
    if (configured < 0) {
        cudaFuncSetAttribute(gemm_f16, cudaFuncAttributeMaxDynamicSharedMemorySize, GSM);
        cudaFuncSetAttribute(attn_mma, cudaFuncAttributeMaxDynamicSharedMemorySize, ASM);
        configured = 1;
    }

    split_x_kernel<<<(NTOT*HIDDEN/8 + 255)/256, 256>>>(c_feat, d_feat);
    pack_both_kernel<<<(NC/32)*(ND/32)*32/256, 256>>>(cd);

    dim3 tb(32, 8);
    transpose_split_kernel<<<dim3(16, 16), tb>>>(Wq, 0, 512, 512);
    transpose_split_kernel<<<dim3(16, 16), tb>>>(Wk, 1, 512, 512);
    transpose_split_kernel<<<dim3(16, 16), tb>>>(Wv, 2, 512, 512);
    transpose_split_kernel<<<dim3(16, 32), tb>>>(Wu, 3, 1024, 512);

    dim3 gg(HIDDEN/128, NTOT/128);
    gemm_f16<<<gg, 256, GSM>>>(bq, 0, 0, 512);
    gemm_f16<<<gg, 256, GSM>>>(bk, 1, 1, 512);
    gemm_f16<<<gg, 256, GSM>>>(bv, 2, 2, 512);

    transpose_v_kernel<<<dim3(HIDDEN/32, NTOT/32), tb>>>();
    qn_kernel<<<(NTOT*NHEAD + 255)/256, 256>>>();
    kmax_kernel<<<dim3(NHEAD, 2), 256>>>();

    attn_mma<<<384, 256, ASM>>>();

    gemm_f16<<<gg, 256, GSM>>>(bu, 3, 3, 1024);

    bn_partial_kernel<<<48, 512>>>();
    bn_final_kernel<<<1, 512>>>(gamma, beta);
    bn_apply_kernel<<<(NTOT*HIDDEN/4 + 255)/256, 256>>>((float4*)out);
}

// round 15
// speedup vs baseline: 1.2586x; 1.2586x over previous
#include <cuda_runtime.h>
#include <cuda_fp16.h>
#include <cstdint>

#define NC   4096
#define ND   2048
#define NTOT 6144
#define HIDDEN 512
#define NHEAD 8
#define HD   64
#define PADH 72   // half-element row stride for smem tiles

__device__ float g_q  [NTOT*HIDDEN];
__device__ float g_k  [NTOT*HIDDEN];
__device__ float g_v  [NTOT*HIDDEN];
__device__ __half g_vTh[HIDDEN*NTOT];    // [hid][row], f16
__device__ float g_att[NTOT*HIDDEN];
__device__ float g_h  [NTOT*HIDDEN];
__device__ __half g_WtQh[HIDDEN*HIDDEN], g_WtQl[HIDDEN*HIDDEN];   // Wt[j][k] hi/lo
__device__ __half g_WtKh[HIDDEN*HIDDEN], g_WtKl[HIDDEN*HIDDEN];
__device__ __half g_WtVh[HIDDEN*HIDDEN], g_WtVl[HIDDEN*HIDDEN];
__device__ __half g_WtUh[HIDDEN*2*HIDDEN], g_WtUl[HIDDEN*2*HIDDEN];
__device__ unsigned g_adj [NC*(ND/32)];
__device__ unsigned g_adjT[ND*(NC/32)];
__device__ float g_qn  [NTOT*NHEAD];
__device__ float g_kmax[2*NHEAD];
__device__ float g_ps[48*HIDDEN];
__device__ float g_pq[48*HIDDEN];
__device__ float g_scale[HIDDEN];
__device__ float g_shift[HIDDEN];

// ---------------- mma helpers -------------------------------------------------
__device__ __forceinline__ uint32_t s2u(const void* p) {
    uint32_t a;
    asm("{ .reg .u64 t; cvta.to.shared.u64 t, %1; cvt.u32.u64 %0, t; }" : "=r"(a) : "l"(p));
    return a;
}
__device__ __forceinline__ void mma_f16(float* d, const unsigned* a, const unsigned* b) {
    asm volatile("mma.sync.aligned.m16n8k16.row.col.f32.f16.f16.f32 "
        "{%0,%1,%2,%3}, {%4,%5,%6,%7}, {%8,%9}, {%0,%1,%2,%3};"
        : "+f"(d[0]), "+f"(d[1]), "+f"(d[2]), "+f"(d[3])
        : "r"(a[0]), "r"(a[1]), "r"(a[2]), "r"(a[3]), "r"(b[0]), "r"(b[1]));
}
__device__ __forceinline__ void ldmA(unsigned* a, uint32_t addr) {
    asm volatile("ldmatrix.sync.aligned.m8n8.x4.shared.b16 {%0,%1,%2,%3}, [%4];"
        : "=r"(a[0]), "=r"(a[1]), "=r"(a[2]), "=r"(a[3]) : "r"(addr));
}
__device__ __forceinline__ void h_split(float x, __half& hi, __half& lo) {
    hi = __float2half_rn(x);
    lo = __float2half_rn(x - __half2float(hi));
}

// ---------------- single-pass adjacency pack (both orientations) -------------
__global__ void pack_both_kernel(const int* __restrict__ cd) {
    int gw = (blockIdx.x * blockDim.x + threadIdx.x) >> 5;
    int lane = threadIdx.x & 31;
    if (gw >= (NC/32) * (ND/32)) return;
    int tr = gw / (ND/32), tc = gw % (ND/32);
    unsigned colbits = 0;
    #pragma unroll 4
    for (int r = 0; r < 32; r++) {
        int row = tr * 32 + r;
        int v = cd[(size_t)row * ND + tc * 32 + lane];
        unsigned word = __ballot_sync(0xFFFFFFFFu, v != 0);
        if (lane == r) g_adj[(size_t)row * (ND/32) + tc] = word;
        colbits |= (v != 0 ? 1u : 0u) << r;
    }
    g_adjT[(size_t)(tc * 32 + lane) * (NC/32) + tr] = colbits;
}

// ---------------- weight transpose + f16 hi/lo split --------------------------
// fused QKV variant: blockIdx.z selects source/dest (all 512x512)
__global__ void transpose_split3_kernel(const float* __restrict__ wq,
                                        const float* __restrict__ wk,
                                        const float* __restrict__ wv) {
    __shared__ float t[32][33];
    int z = blockIdx.z;
    const float* in = (z == 0) ? wq : (z == 1) ? wk : wv;
    __half* outh = (z == 0) ? g_WtQh : (z == 1) ? g_WtKh : g_WtVh;
    __half* outl = (z == 0) ? g_WtQl : (z == 1) ? g_WtKl : g_WtVl;
    int bx = blockIdx.x * 32, by = blockIdx.y * 32;
    int x = bx + threadIdx.x, y = by + threadIdx.y;
    #pragma unroll
    for (int i = 0; i < 32; i += 8) t[threadIdx.y + i][threadIdx.x] = in[(size_t)(y + i) * HIDDEN + x];
    __syncthreads();
    x = by + threadIdx.x; y = bx + threadIdx.y;
    #pragma unroll
    for (int i = 0; i < 32; i += 8) {
        float v = t[threadIdx.x][threadIdx.y + i];
        __half hi, lo; h_split(v, hi, lo);
        outh[(size_t)(y + i) * HIDDEN + x] = hi;
        outl[(size_t)(y + i) * HIDDEN + x] = lo;
    }
}
// Wu: [1024 rows][512 cols] -> WtU[512][1024]
__global__ void transpose_splitU_kernel(const float* __restrict__ in) {
    __shared__ float t[32][33];
    int bx = blockIdx.x * 32, by = blockIdx.y * 32;
    int x = bx + threadIdx.x, y = by + threadIdx.y;
    #pragma unroll
    for (int i = 0; i < 32; i += 8) t[threadIdx.y + i][threadIdx.x] = in[(size_t)(y + i) * HIDDEN + x];
    __syncthreads();
    x = by + threadIdx.x; y = bx + threadIdx.y;
    #pragma unroll
    for (int i = 0; i < 32; i += 8) {
        float v = t[threadIdx.x][threadIdx.y + i];
        __half hi, lo; h_split(v, hi, lo);
        g_WtUh[(size_t)(y + i) * 1024 + x] = hi;
        g_WtUl[(size_t)(y + i) * 1024 + x] = lo;
    }
}

// ---------------- V transpose fp32 -> f16: g_vTh[hid][row] --------------------
__global__ void transpose_v_kernel() {
    __shared__ float t[32][33];
    int bx = blockIdx.x * 32, by = blockIdx.y * 32;  // bx: hid, by: token
    int x = bx + threadIdx.x, y = by + threadIdx.y;
    #pragma unroll
    for (int i = 0; i < 32; i += 8) t[threadIdx.y + i][threadIdx.x] = g_v[(size_t)(y + i) * HIDDEN + x];
    __syncthreads();
    x = by + threadIdx.x; y = bx + threadIdx.y;
    #pragma unroll
    for (int i = 0; i < 32; i += 8)
        g_vTh[(size_t)(y + i) * NTOT + x] = __float2half_rn(t[threadIdx.x][threadIdx.y + i]);
}

// ---------------- norms / bounds ----------------------------------------------
__global__ void qn_kernel() {
    int idx = blockIdx.x * blockDim.x + threadIdx.x;
    if (idx >= NTOT * NHEAD) return;
    int row = idx >> 3, h = idx & 7;
    const float4* p = (const float4*)(g_q + (size_t)row * HIDDEN + h * HD);
    float s = 0.f;
    #pragma unroll
    for (int i = 0; i < 16; i++) { float4 v = p[i]; s += v.x*v.x + v.y*v.y + v.z*v.z + v.w*v.w; }
    g_qn[idx] = sqrtf(s);
}
__global__ void kmax_kernel() {
    int head = blockIdx.x, side = blockIdx.y;
    int r0 = side ? NC : 0, nr = side ? ND : NC;
    int tid = threadIdx.x;
    float mx = 0.f;
    for (int r = tid; r < nr; r += 256) {
        const float4* p = (const float4*)(g_k + (size_t)(r0 + r) * HIDDEN + head * HD);
        float s = 0.f;
        #pragma unroll
        for (int i = 0; i < 16; i++) { float4 v = p[i]; s += v.x*v.x + v.y*v.y + v.z*v.z + v.w*v.w; }
        mx = fmaxf(mx, s);
    }
    __shared__ float red[256];
    red[tid] = mx; __syncthreads();
    for (int o = 128; o; o >>= 1) { if (tid < o) red[tid] = fmaxf(red[tid], red[tid + o]); __syncthreads(); }
    if (tid == 0) g_kmax[side * 8 + head] = sqrtf(red[0]);
}

// ---------------- f16x3 mma GEMM body (shared by QKV-fused and U) -------------
__device__ __forceinline__ void gemm_body(
    const float* __restrict__ cf, const float* __restrict__ df,
    const __half* __restrict__ Wth, const __half* __restrict__ Wtl,
    const float* __restrict__ bias, float* __restrict__ C, int Ktot)
{
    extern __shared__ __half sh[];
    __half* Ahi = sh;                    // [128][PADH]
    __half* Alo = Ahi + 128*PADH;
    __half* Bhi = Alo + 128*PADH;        // [128 n][PADH]
    __half* Blo = Bhi + 128*PADH;

    const int tid = threadIdx.x, lane = tid & 31, w = tid >> 5;
    const int wm = w & 3, wn = w >> 2;
    const int rowBase = blockIdx.y * 128, colBase = blockIdx.x * 128;

    float acc[2][8][4];
    #pragma unroll
    for (int mi = 0; mi < 2; mi++)
        #pragma unroll
        for (int nt = 0; nt < 8; nt++)
            #pragma unroll
            for (int j = 0; j < 4; j++) acc[mi][nt][j] = 0.f;

    uint32_t addrA[2];
    #pragma unroll
    for (int mi = 0; mi < 2; mi++)
        addrA[mi] = s2u(Ahi) + (uint32_t)(((wm*32 + mi*16 + (lane & 15)) * PADH + (lane >> 4) * 8) * 2);
    const uint32_t dAlo = (uint32_t)(128 * PADH * 2);

    for (int kc = 0; kc < Ktot / 64; kc++) {
        #pragma unroll
        for (int i = 0; i < 8; i++) {
            int f = tid + i * 256;
            int r = f >> 4, c = (f & 15) * 4;
            int row = rowBase + r, kk = kc * 64 + c;
            const float* src = (kk < HIDDEN)
                ? ((row < NC) ? cf + (size_t)row * HIDDEN + kk
                              : df + (size_t)(row - NC) * HIDDEN + kk)
                : g_att + (size_t)row * HIDDEN + (kk - HIDDEN);
            float4 v = *(const float4*)src;
            __half h0,h1,h2,h3,l0,l1,l2,l3;
            h_split(v.x,h0,l0); h_split(v.y,h1,l1); h_split(v.z,h2,l2); h_split(v.w,h3,l3);
            __half* ah = Ahi + r * PADH + c;
            __half* al = Alo + r * PADH + c;
            ah[0]=h0; ah[1]=h1; ah[2]=h2; ah[3]=h3;
            al[0]=l0; al[1]=l1; al[2]=l2; al[3]=l3;
        }
        // B tile 128(n)x64(k): pre-split, pure uint4 copies
        #pragma unroll
        for (int i = 0; i < 4; i++) {
            int f = tid + i * 256;
            int r = f >> 3, c = (f & 7) * 8;
            size_t gofs = (size_t)(colBase + r) * Ktot + kc * 64 + c;
            *(uint4*)(Bhi + r * PADH + c) = *(const uint4*)(Wth + gofs);
            *(uint4*)(Blo + r * PADH + c) = *(const uint4*)(Wtl + gofs);
        }
        __syncthreads();

        #pragma unroll
        for (int ks = 0; ks < 4; ks++) {
            unsigned ahi[2][4], alo[2][4];
            #pragma unroll
            for (int mi = 0; mi < 2; mi++) {
                ldmA(ahi[mi], addrA[mi] + ks * 32);
                ldmA(alo[mi], addrA[mi] + dAlo + ks * 32);
            }
            #pragma unroll
            for (int nt = 0; nt < 8; nt++) {
                const __half* bp = Bhi + (wn*64 + nt*8 + (lane >> 2)) * PADH + ks*16 + (lane & 3)*2;
                const __half* bq = Blo + (wn*64 + nt*8 + (lane >> 2)) * PADH + ks*16 + (lane & 3)*2;
                unsigned bh[2] = { *(const unsigned*)bp, *(const unsigned*)(bp + 8) };
                unsigned bl[2] = { *(const unsigned*)bq, *(const unsigned*)(bq + 8) };
                #pragma unroll
                for (int mi = 0; mi < 2; mi++) {
                    mma_f16(acc[mi][nt], ahi[mi], bh);
                    mma_f16(acc[mi][nt], ahi[mi], bl);
                    mma_f16(acc[mi][nt], alo[mi], bh);
                }
            }
        }
        __syncthreads();
    }
    #pragma unroll
    for (int mi = 0; mi < 2; mi++) {
        int row = rowBase + wm*32 + mi*16 + (lane >> 2);
        #pragma unroll
        for (int nt = 0; nt < 8; nt++) {
            int col = colBase + wn*64 + nt*8 + (lane & 3)*2;
            float b0 = bias[col], b1 = bias[col + 1];
            *(float2*)(C + (size_t)row * HIDDEN + col) =
                make_float2(acc[mi][nt][0] + b0, acc[mi][nt][1] + b1);
            *(float2*)(C + (size_t)(row + 8) * HIDDEN + col) =
                make_float2(acc[mi][nt][2] + b0, acc[mi][nt][3] + b1);
        }
    }
}

// fused QKV: grid (4, 48, 3), blockIdx.z selects projection
__global__ void __launch_bounds__(256, 2)
gemm_qkv(const float* __restrict__ cf, const float* __restrict__ df,
         const float* __restrict__ bq, const float* __restrict__ bk,
         const float* __restrict__ bv)
{
    int z = blockIdx.z;
    const __half* Wth = (z == 0) ? g_WtQh : (z == 1) ? g_WtKh : g_WtVh;
    const __half* Wtl = (z == 0) ? g_WtQl : (z == 1) ? g_WtKl : g_WtVl;
    const float* bias = (z == 0) ? bq : (z == 1) ? bk : bv;
    float* C = (z == 0) ? g_q : (z == 1) ? g_k : g_v;
    gemm_body(cf, df, Wth, Wtl, bias, C, 512);
}

__global__ void __launch_bounds__(256, 2)
gemm_u(const float* __restrict__ cf, const float* __restrict__ df,
       const float* __restrict__ bu)
{
    gemm_body(cf, df, g_WtUh, g_WtUl, bu, g_h, 1024);
}

// ---------------- f16 mma flash attention (R8 shape, occupancy 2) -------------
// flat grid 384: bid<128 d-side (head=bid>>4, qt=bid&15), else c-side
// (r=bid-128, head=r>>5, qt=r&31). 256 thr, warp w: 16 q rows.
__global__ void __launch_bounds__(256, 2)
attn_mma()
{
    extern __shared__ __half smh[];
    __half* Qhi = smh;                   // [128][PADH]
    __half* Qlo = Qhi + 128*PADH;
    __half* Khi = Qlo + 128*PADH;        // [64 key][PADH d]
    __half* Klo = Khi + 64*PADH;
    __half* Vt  = Klo + 64*PADH;         // [64 d][PADH key]
    __half* Pm  = Vt  + 64*PADH;         // [128][PADH]
    unsigned* Mw = (unsigned*)(Pm + 128*PADH);   // [128][2]

    const int tid = threadIdx.x, lane = tid & 31, w = tid >> 5;
    const int bid = blockIdx.x;
    const bool dside = (bid < 128);
    int head, qt;
    if (dside) { head = bid >> 4; qt = bid & 15; }
    else { int r = bid - 128; head = r >> 5; qt = r & 31; }
    const int qbase = dside ? NC + qt * 128 : qt * 128;
    const int kbase = dside ? 0 : NC;
    const int nkeys = dside ? NC : ND;
    const int qr0 = w * 16;

    // load Q tile, split hi/lo
    #pragma unroll
    for (int i = 0; i < 8; i++) {
        int f = tid + i * 256;
        int r = f >> 4, c = (f & 15) * 4;
        float4 v = *(const float4*)(g_q + (size_t)(qbase + r) * HIDDEN + head * HD + c);
        __half h0,h1,h2,h3,l0,l1,l2,l3;
        h_split(v.x,h0,l0); h_split(v.y,h1,l1); h_split(v.z,h2,l2); h_split(v.w,h3,l3);
        __half* qh = Qhi + r * PADH + c;
        __half* ql = Qlo + r * PADH + c;
        qh[0]=h0; qh[1]=h1; qh[2]=h2; qh[3]=h3;
        ql[0]=l0; ql[1]=l1; ql[2]=l2; ql[3]=l3;
    }
    __syncthreads();

    const int rA = qr0 + (lane >> 2), rB = rA + 8;
    const float kmx = g_kmax[(dside ? 0 : 8) + head];
    const float MqA = g_qn[(qbase + rA) * NHEAD + head] * kmx * 0.125f;
    const float MqB = g_qn[(qbase + rB) * NHEAD + head] * kmx * 0.125f;
    const unsigned* mb = dside ? g_adjT + (size_t)(qbase - NC + tid) * (NC/32)
                               : g_adj  + (size_t)(qbase + tid) * (ND/32);

    const uint32_t aoff = (uint32_t)(((qr0 + (lane & 15)) * PADH + (lane >> 4) * 8) * 2);
    const uint32_t addrQhi = s2u(Qhi) + aoff;
    const uint32_t addrQlo = s2u(Qlo) + aoff;
    const uint32_t addrP   = s2u(Pm)  + aoff;

    float oacc[8][4];
    #pragma unroll
    for (int n = 0; n < 8; n++)
        #pragma unroll
        for (int j = 0; j < 4; j++) oacc[n][j] = 0.f;
    float lA = 0.f, lB = 0.f;

    #pragma unroll 1
    for (int kb = 0; kb < nkeys; kb += 64) {
        // K tile [key][d] split hi/lo (row-major from g_k)
        #pragma unroll
        for (int i = 0; i < 4; i++) {
            int f = tid + i * 256;
            int r = f >> 4, c = (f & 15) * 4;
            float4 v = *(const float4*)(g_k + (size_t)(kbase + kb + r) * HIDDEN + head * HD + c);
            __half h0,h1,h2,h3,l0,l1,l2,l3;
            h_split(v.x,h0,l0); h_split(v.y,h1,l1); h_split(v.z,h2,l2); h_split(v.w,h3,l3);
            __half* kh = Khi + r * PADH + c;
            __half* kl = Klo + r * PADH + c;
            kh[0]=h0; kh[1]=h1; kh[2]=h2; kh[3]=h3;
            kl[0]=l0; kl[1]=l1; kl[2]=l2; kl[3]=l3;
        }
        // V^T tile [d][key]: pre-converted f16, pure uint4 copies
        #pragma unroll
        for (int i = 0; i < 2; i++) {
            int f = tid + i * 256;
            int r = f >> 3, c = (f & 7) * 8;
            *(uint4*)(Vt + r * PADH + c) =
                *(const uint4*)(g_vTh + (size_t)(head * HD + r) * NTOT + kbase + kb + c);
        }
        if (tid < 128) {
            Mw[tid * 2]     = mb[(kb >> 5)];
            Mw[tid * 2 + 1] = mb[(kb >> 5) + 1];
        }
        __syncthreads();

        // ---- S = Q K^T (f16 x3) ----
        float sacc[8][4];
        #pragma unroll
        for (int n = 0; n < 8; n++)
            #pragma unroll
            for (int j = 0; j < 4; j++) sacc[n][j] = 0.f;
        #pragma unroll
        for (int ks = 0; ks < 4; ks++) {
            unsigned ahi[4], alo[4];
            ldmA(ahi, addrQhi + ks * 32);
            ldmA(alo, addrQlo + ks * 32);
            #pragma unroll
            for (int nt = 0; nt < 8; nt++) {
                const __half* bp = Khi + (nt*8 + (lane >> 2)) * PADH + ks*16 + (lane & 3)*2;
                const __half* bq = Klo + (nt*8 + (lane >> 2)) * PADH + ks*16 + (lane & 3)*2;
                unsigned bh[2] = { *(const unsigned*)bp, *(const unsigned*)(bp + 8) };
                unsigned bl[2] = { *(const unsigned*)bq, *(const unsigned*)(bq + 8) };
                mma_f16(sacc[nt], ahi, bh);
                mma_f16(sacc[nt], ahi, bl);
                mma_f16(sacc[nt], alo, bh);
            }
        }
        // ---- softmax epilogue (single pass, bound-shifted) ----
        #pragma unroll
        for (int n = 0; n < 8; n++) {
            int colb = n * 8 + 2 * (lane & 3);
            unsigned mwA = Mw[rA * 2 + (colb >> 5)];
            unsigned mwB = Mw[rB * 2 + (colb >> 5)];
            int bit = colb & 31;
            float p0 = ((mwA >> bit) & 1u)       ? __expf(sacc[n][0] * 0.125f - MqA) : 0.f;
            float p1 = ((mwA >> (bit + 1)) & 1u) ? __expf(sacc[n][1] * 0.125f - MqA) : 0.f;
            float p2 = ((mwB >> bit) & 1u)       ? __expf(sacc[n][2] * 0.125f - MqB) : 0.f;
            float p3 = ((mwB >> (bit + 1)) & 1u) ? __expf(sacc[n][3] * 0.125f - MqB) : 0.f;
            lA += p0 + p1; lB += p2 + p3;
            *(__half2*)(Pm + rA * PADH + colb) = __floats2half2_rn(p0, p1);
            *(__half2*)(Pm + rB * PADH + colb) = __floats2half2_rn(p2, p3);
        }
        __syncwarp();
        // ---- O += P V (single f16) ----
        #pragma unroll
        for (int ks = 0; ks < 4; ks++) {
            unsigned ap[4];
            ldmA(ap, addrP + ks * 32);
            #pragma unroll
            for (int nt = 0; nt < 8; nt++) {
                const __half* vp = Vt + (nt*8 + (lane >> 2)) * PADH + ks*16 + (lane & 3)*2;
                unsigned bv[2] = { *(const unsigned*)vp, *(const unsigned*)(vp + 8) };
                mma_f16(oacc[nt], ap, bv);
            }
        }
        __syncthreads();
    }

    lA += __shfl_xor_sync(0xFFFFFFFFu, lA, 1);
    lA += __shfl_xor_sync(0xFFFFFFFFu, lA, 2);
    lB += __shfl_xor_sync(0xFFFFFFFFu, lB, 1);
    lB += __shfl_xor_sync(0xFFFFFFFFu, lB, 2);
    float invA = (lA > 0.f) ? 1.f / lA : 0.f;
    float invB = (lB > 0.f) ? 1.f / lB : 0.f;

    #pragma unroll
    for (int n = 0; n < 8; n++) {
        int colb = head * HD + n * 8 + 2 * (lane & 3);
        *(float2*)(g_att + (size_t)(qbase + rA) * HIDDEN + colb) =
            make_float2(oacc[n][0] * invA, oacc[n][1] * invA);
        *(float2*)(g_att + (size_t)(qbase + rB) * HIDDEN + colb) =
            make_float2(oacc[n][2] * invB, oacc[n][3] * invB);
    }
}

// ---------------- BatchNorm + ReLU -------------------------------------------
__global__ void bn_partial_kernel() {
    int c = threadIdx.x, g = blockIdx.x;
    float s = 0.f, q = 0.f;
    const float* p = g_h + (size_t)g * 128 * HIDDEN + c;
    #pragma unroll 4
    for (int r = 0; r < 128; r++) { float x = p[(size_t)r * HIDDEN]; s += x; q += x * x; }
    g_ps[g * HIDDEN + c] = s;
    g_pq[g * HIDDEN + c] = q;
}
__global__ void bn_final_kernel(const float* __restrict__ gamma, const float* __restrict__ beta) {
    int c = threadIdx.x;
    float s = 0.f, q = 0.f;
    #pragma unroll
    for (int g = 0; g < 48; g++) { s += g_ps[g * HIDDEN + c]; q += g_pq[g * HIDDEN + c]; }
    const float invN = 1.f / (float)NTOT;
    float mu = s * invN, var = q * invN - mu * mu;
    float sc = gamma[c] * rsqrtf(var + 1e-5f);
    g_scale[c] = sc; g_shift[c] = beta[c] - mu * sc;
}
__global__ void bn_apply_kernel(float4* __restrict__ out) {
    int i = blockIdx.x * blockDim.x + threadIdx.x;
    float4 hv = ((const float4*)g_h)[i];
    int c = (i * 4) & (HIDDEN - 1);
    out[i] = make_float4(fmaxf(0.f, hv.x * g_scale[c]   + g_shift[c]),
                         fmaxf(0.f, hv.y * g_scale[c+1] + g_shift[c+1]),
                         fmaxf(0.f, hv.z * g_scale[c+2] + g_shift[c+2]),
                         fmaxf(0.f, hv.w * g_scale[c+3] + g_shift[c+3]));
}

// ---------------- launch ------------------------------------------------------
extern "C" void kernel_launch(void* const* d_in, const int* in_sizes, int n_in,
                              void* d_out, int out_size)
{
    const float* c_feat = (const float*)d_in[0];
    const float* d_feat = (const float*)d_in[1];
    const int*   cd     = (const int*)  d_in[2];
    const float* Wq = (const float*)d_in[3];  const float* bq = (const float*)d_in[4];
    const float* Wk = (const float*)d_in[5];  const float* bk = (const float*)d_in[6];
    const float* Wv = (const float*)d_in[7];  const float* bv = (const float*)d_in[8];
    const float* Wu = (const float*)d_in[9];  const float* bu = (const float*)d_in[10];
    const float* gamma = (const float*)d_in[11];
    const float* beta  = (const float*)d_in[12];
    float* out = (float*)d_out;

    const int GSM = 4 * 128 * PADH * 2;                          // 73728 B
    const int ASM = (128*2 + 64*3 + 128) * PADH * 2 + 128*2*4;   // 83968 B
    static int configured = -1;
    if (configured < 0) {
        cudaFuncSetAttribute(gemm_qkv, cudaFuncAttributeMaxDynamicSharedMemorySize, GSM);
        cudaFuncSetAttribute(gemm_u,   cudaFuncAttributeMaxDynamicSharedMemorySize, GSM);
        cudaFuncSetAttribute(attn_mma, cudaFuncAttributeMaxDynamicSharedMemorySize, ASM);
        configured = 1;
    }

    pack_both_kernel<<<(NC/32)*(ND/32)*32/256, 256>>>(cd);

    dim3 tb(32, 8);
    transpose_split3_kernel<<<dim3(16, 16, 3), tb>>>(Wq, Wk, Wv);
    transpose_splitU_kernel<<<dim3(16, 32), tb>>>(Wu);

    gemm_qkv<<<dim3(HIDDEN/128, NTOT/128, 3), 256, GSM>>>(c_feat, d_feat, bq, bk, bv);

    transpose_v_kernel<<<dim3(HIDDEN/32, NTOT/32), tb>>>();
    qn_kernel<<<(NTOT*NHEAD + 255)/256, 256>>>();
    kmax_kernel<<<dim3(NHEAD, 2), 256>>>();

    attn_mma<<<384, 256, ASM>>>();

    gemm_u<<<dim3(HIDDEN/128, NTOT/128), 256, GSM>>>(c_feat, d_feat, bu);

    bn_partial_kernel<<<48, 512>>>();
    bn_final_kernel<<<1, 512>>>(gamma, beta);
    bn_apply_kernel<<<(NTOT*HIDDEN/4 + 255)/256, 256>>>((float4*)out);
}